// round 13
// baseline (speedup 1.0000x reference)
#include <cuda_runtime.h>
#include <math.h>

#define SEQ   40
#define H     4096
#define OUT   128
#define NBLK  256
#define NTHR  512
#define JPB   16                  // hidden indices per block (= warps per block)
#define RPB   64                  // rows per block (16 j x 4 gates)
#define ROWS  (4 * H)
#define CH_B  16384               // bytes per chunk (64 rows x 256 cols)
#define NCHUNK 16
#define SCH   6                   // chunks 0..5 resident in smem (96 KB)
#define BLOCK_WQ (RPB * H)        // 256 KB s8 weights per block
#define SMEM_W (SCH * CH_B)       // 98304

// ---- persistent device state ----
__device__ unsigned g_hw[2][H];                                  // tagged h: (epoch16<<16)|h_s16
__device__ unsigned g_run;                                       // launch counter (quant bumps)
__device__ float    g_scale[ROWS];                               // per-row dequant scale
__device__ __align__(256) unsigned char g_wq[(size_t)NBLK * BLOCK_WQ]; // 67MB s8

// ---------------- quant; paired-row layout ----------------
// [B=j>>4][chunk][warp=j&15][pair=gate>>1][lane 16B: rows(2p,2p+1) cols 8l..8l+7]
__global__ __launch_bounds__(256) void quant_kernel(const float* __restrict__ w_hh) {
    __shared__ float wmax[8];
    const int r    = blockIdx.x;             // gate row (gate*H + j)
    const int tid  = threadIdx.x;
    const int lane = tid & 31, wrp = tid >> 5;

    if (r == 0 && tid == 0) g_run = g_run + 1;   // epoch bump, once per launch

    const float4* rp = (const float4*)(w_hh + (size_t)r * H) + tid * 4;
    const float4 vs[4] = {__ldg(rp), __ldg(rp + 1), __ldg(rp + 2), __ldg(rp + 3)};

    float m = 0.0f;
    #pragma unroll
    for (int q = 0; q < 4; ++q)
        m = fmaxf(m, fmaxf(fmaxf(fabsf(vs[q].x), fabsf(vs[q].y)),
                           fmaxf(fabsf(vs[q].z), fabsf(vs[q].w))));
    #pragma unroll
    for (int o = 16; o > 0; o >>= 1) m = fmaxf(m, __shfl_xor_sync(0xffffffffu, m, o));
    if (lane == 0) wmax[wrp] = m;
    __syncthreads();
    float mx = wmax[0];
    #pragma unroll
    for (int w = 1; w < 8; ++w) mx = fmaxf(mx, wmax[w]);
    if (tid == 0) g_scale[r] = mx * (1.0f / 127.0f);
    const float inv = (mx > 0.0f) ? 127.0f / mx : 0.0f;

    unsigned b[16];
    #pragma unroll
    for (int q = 0; q < 4; ++q) {
        b[4 * q + 0] = __float_as_uint(fmaf(vs[q].x, inv, 8388736.0f));
        b[4 * q + 1] = __float_as_uint(fmaf(vs[q].y, inv, 8388736.0f));
        b[4 * q + 2] = __float_as_uint(fmaf(vs[q].z, inv, 8388736.0f));
        b[4 * q + 3] = __float_as_uint(fmaf(vs[q].w, inv, 8388736.0f));
    }
    uint4 o;
    #pragma unroll
    for (int q = 0; q < 4; ++q) {
        unsigned t0 = __byte_perm(b[4 * q + 0], b[4 * q + 1], 0x0040);
        unsigned t1 = __byte_perm(b[4 * q + 2], b[4 * q + 3], 0x0040);
        ((unsigned*)&o)[q] = __byte_perm(t0, t1, 0x5410) ^ 0x80808080u;
    }
    const int j = r & (H - 1), gate = r >> 12;
    const int B = j >> 4;
    const int wid_ = j & 15;
    const int p = gate >> 1, rp_ = gate & 1;
    const int chunk = tid >> 4;
    const int lpos = (tid & 15) * 2;
    unsigned char* dst = g_wq + (size_t)B * BLOCK_WQ + (size_t)chunk * CH_B
                       + wid_ * 1024 + p * 512 + rp_ * 8;
    *(uint2*)(dst + lpos * 16)       = make_uint2(o.x, o.y);
    *(uint2*)(dst + (lpos + 1) * 16) = make_uint2(o.z, o.w);
}

#define DOPAIR(p, Q) do {                                                 \
    acc[2*(p)]   = __dp2a_lo((int)hv.x, (int)(Q).x, acc[2*(p)]);          \
    acc[2*(p)]   = __dp2a_hi((int)hv.y, (int)(Q).x, acc[2*(p)]);          \
    acc[2*(p)]   = __dp2a_lo((int)hv.z, (int)(Q).y, acc[2*(p)]);          \
    acc[2*(p)]   = __dp2a_hi((int)hv.w, (int)(Q).y, acc[2*(p)]);          \
    acc[2*(p)+1] = __dp2a_lo((int)hv.x, (int)(Q).z, acc[2*(p)+1]);        \
    acc[2*(p)+1] = __dp2a_hi((int)hv.y, (int)(Q).z, acc[2*(p)+1]);        \
    acc[2*(p)+1] = __dp2a_lo((int)hv.z, (int)(Q).w, acc[2*(p)+1]);        \
    acc[2*(p)+1] = __dp2a_hi((int)hv.w, (int)(Q).w, acc[2*(p)+1]);        \
} while (0)

#define DOCHUNK_SM(cc) do {                                               \
    const uint4 hv = *(const uint4*)(hq + (cc) * 128 + 4 * lane);         \
    const unsigned char* _c = wsm + (size_t)(cc) * CH_B + wid * 1024 + lane * 16; \
    const uint4 q0 = *(const uint4*)(_c);                                 \
    const uint4 q1 = *(const uint4*)(_c + 512);                           \
    DOPAIR(0, q0); DOPAIR(1, q1);                                         \
} while (0)

#define DOCHUNK_SB(cc, SB) do {                                           \
    const uint4 hv = *(const uint4*)(hq + (cc) * 128 + 4 * lane);         \
    DOPAIR(0, SB[0]); DOPAIR(1, SB[1]);                                   \
} while (0)

#define LDSB(dst, cc) do {                                                \
    const unsigned char* _p = wsrc + (size_t)(cc) * CH_B + wid * 1024 + lane * 16; \
    dst[0] = __ldg((const uint4*)(_p));                                   \
    dst[1] = __ldg((const uint4*)(_p + 512)); } while (0)

__device__ __forceinline__ float sigf(float v) { return 1.0f / (1.0f + __expf(-v)); }

// ---------------- persistent LSTM kernel (2 blocks/SM) ----------------
__global__ __launch_bounds__(NTHR, 2)
void lstm_persistent_kernel(const float* __restrict__ x,
                            const float* __restrict__ w_ih,
                            const float* __restrict__ b_ih,
                            const float* __restrict__ b_hh,
                            const float* __restrict__ dense_w,
                            const float* __restrict__ dense_b,
                            float* __restrict__ out) {
    extern __shared__ unsigned char wsm[];       // 96 KB resident weights (chunks 0..5)
    __shared__ unsigned hq[H / 2];               // 8 KB packed h_{t-1}
    __shared__ float xs[SEQ];
    __shared__ float red[NTHR / 32];

    const int tid  = threadIdx.x;
    const int lane = tid & 31;
    const int wid  = tid >> 5;                   // warp owns j = j0 + wid (all 4 gates)
    const int j0   = blockIdx.x * JPB;
    const int j    = j0 + wid;
    const unsigned char* wsrc = g_wq + (size_t)blockIdx.x * BLOCK_WQ;

    // per-lane gate constants: lane g (mod 4) holds gate g's scalars
    const int grow = (lane & 3) * H + j;
    const float wih_l  = __ldg(w_ih + grow);
    const float bsum_l = __ldg(b_ih + grow) + __ldg(b_hh + grow);
    const float scl_l  = __ldg(g_scale + grow) * (1.0f / 32767.0f);
    if (tid < SEQ) xs[tid] = x[tid];

    // copy smem-resident chunks 0..5
    {
        const uint4* gsrc = (const uint4*)wsrc;
        uint4* d = (uint4*)wsm;
        #pragma unroll
        for (int i = 0; i < SMEM_W / 16 / NTHR; ++i)
            d[tid + i * NTHR] = __ldg(gsrc + tid + i * NTHR);
    }

    const unsigned run = *(volatile unsigned*)&g_run;   // written by quant kernel
    float c_reg = 0.0f;

    for (int t = 0; t < SEQ; ++t) {
        int rsel = 0;
        if (t > 0) {
            // prefetch first four streamed chunks (independent of h)
            uint4 sb0[2], sb1[2], sb2[2], sb3[2];
            LDSB(sb0, 6); LDSB(sb1, 7); LDSB(sb2, 8); LDSB(sb3, 9);

            // self-synchronizing staging: poll tagged words directly (no fences)
            {
                const unsigned want = (run * 64u + (unsigned)t) & 0xffffu;
                const unsigned* pw = g_hw[(t - 1) & 1] + 8 * tid;
                unsigned w0, w1, w2, w3, w4, w5, w6, w7;
                for (;;) {
                    asm volatile("ld.volatile.global.v4.u32 {%0,%1,%2,%3}, [%4];"
                                 : "=r"(w0), "=r"(w1), "=r"(w2), "=r"(w3) : "l"(pw));
                    asm volatile("ld.volatile.global.v4.u32 {%0,%1,%2,%3}, [%4];"
                                 : "=r"(w4), "=r"(w5), "=r"(w6), "=r"(w7) : "l"(pw + 4));
                    if ((w0 >> 16) == want && (w1 >> 16) == want &&
                        (w2 >> 16) == want && (w3 >> 16) == want &&
                        (w4 >> 16) == want && (w5 >> 16) == want &&
                        (w6 >> 16) == want && (w7 >> 16) == want) break;
                }
                uint4 pk;
                pk.x = __byte_perm(w0, w1, 0x5410);
                pk.y = __byte_perm(w2, w3, 0x5410);
                pk.z = __byte_perm(w4, w5, 0x5410);
                pk.w = __byte_perm(w6, w7, 0x5410);
                ((uint4*)hq)[tid] = pk;
            }
            __syncthreads();                     // bar A: hq staged

            int acc[4] = {0, 0, 0, 0};
            DOCHUNK_SM(0); DOCHUNK_SM(1); DOCHUNK_SM(2);
            DOCHUNK_SM(3); DOCHUNK_SM(4); DOCHUNK_SM(5);
            DOCHUNK_SB(6,  sb0); LDSB(sb0, 10);
            DOCHUNK_SB(7,  sb1); LDSB(sb1, 11);
            DOCHUNK_SB(8,  sb2); LDSB(sb2, 12);
            DOCHUNK_SB(9,  sb3); LDSB(sb3, 13);
            DOCHUNK_SB(10, sb0); LDSB(sb0, 14);
            DOCHUNK_SB(11, sb1); LDSB(sb1, 15);
            DOCHUNK_SB(12, sb2);
            DOCHUNK_SB(13, sb3);
            DOCHUNK_SB(14, sb0);
            DOCHUNK_SB(15, sb1);

            const int r0 = __reduce_add_sync(0xffffffffu, acc[0]);
            const int r1 = __reduce_add_sync(0xffffffffu, acc[1]);
            const int r2 = __reduce_add_sync(0xffffffffu, acc[2]);
            const int r3 = __reduce_add_sync(0xffffffffu, acc[3]);
            rsel = (lane == 1) ? r1 : (lane == 2) ? r2 : (lane == 3) ? r3 : r0;
        }

        // gate-parallel tail: lanes 0..3 evaluate their gate's activation
        {
            const float xt = xs[t];
            const float v  = fmaf(wih_l, xt, bsum_l) + __int2float_rn(rsel) * scl_l;
            const float act = (lane == 2) ? tanhf(v) : sigf(v);
            const float a1 = __shfl_sync(0xffffffffu, act, 1);
            const float a2 = __shfl_sync(0xffffffffu, act, 2);
            const float a3 = __shfl_sync(0xffffffffu, act, 3);
            if (lane == 0) {
                const float c = a1 * c_reg + act * a2;   // sig(f)*c + sig(i)*tanh(g)
                c_reg = c;
                const float h = a3 * tanhf(c);
                const unsigned hu = (unsigned)(unsigned short)
                                    (short)__float2int_rn(h * 32767.0f);
                const unsigned tag = (run * 64u + (unsigned)(t + 1)) & 0xffffu;
                *(volatile unsigned*)&g_hw[t & 1][j] = (tag << 16) | hu;  // atomic word
            }
        }
        __syncthreads();                         // bar B: hq free for next staging
    }

    // dense epilogue: blocks 0..OUT-1; h_last from tagged words (buffer 1, tag run*64+SEQ)
    if (blockIdx.x < OUT) {
        const unsigned want = (run * 64u + (unsigned)SEQ) & 0xffffu;
        const unsigned* pw = g_hw[(SEQ - 1) & 1] + 8 * tid;
        unsigned w0, w1, w2, w3, w4, w5, w6, w7;
        for (;;) {
            asm volatile("ld.volatile.global.v4.u32 {%0,%1,%2,%3}, [%4];"
                         : "=r"(w0), "=r"(w1), "=r"(w2), "=r"(w3) : "l"(pw));
            asm volatile("ld.volatile.global.v4.u32 {%0,%1,%2,%3}, [%4];"
                         : "=r"(w4), "=r"(w5), "=r"(w6), "=r"(w7) : "l"(pw + 4));
            if ((w0 >> 16) == want && (w1 >> 16) == want &&
                (w2 >> 16) == want && (w3 >> 16) == want &&
                (w4 >> 16) == want && (w5 >> 16) == want &&
                (w6 >> 16) == want && (w7 >> 16) == want) break;
        }
        const float s = 1.0f / 32767.0f;
        float hv[8] = {
            (float)(short)(w0 & 0xffffu) * s, (float)(short)(w1 & 0xffffu) * s,
            (float)(short)(w2 & 0xffffu) * s, (float)(short)(w3 & 0xffffu) * s,
            (float)(short)(w4 & 0xffffu) * s, (float)(short)(w5 & 0xffffu) * s,
            (float)(short)(w6 & 0xffffu) * s, (float)(short)(w7 & 0xffffu) * s };
        const float4* wr = (const float4*)(dense_w + (size_t)blockIdx.x * H + 8 * tid);
        const float4 wa = __ldg(wr), wb = __ldg(wr + 1);
        float acc = wa.x * hv[0] + wa.y * hv[1] + wa.z * hv[2] + wa.w * hv[3]
                  + wb.x * hv[4] + wb.y * hv[5] + wb.z * hv[6] + wb.w * hv[7];
        #pragma unroll
        for (int o = 16; o > 0; o >>= 1)
            acc += __shfl_down_sync(0xffffffffu, acc, o);
        if (lane == 0) red[wid] = acc;
        __syncthreads();
        if (tid == 0) {
            float s2 = 0.0f;
            #pragma unroll
            for (int w = 0; w < NTHR / 32; ++w) s2 += red[w];
            out[blockIdx.x] = s2 + dense_b[blockIdx.x];
        }
    }
}

extern "C" void kernel_launch(void* const* d_in, const int* in_sizes, int n_in,
                              void* d_out, int out_size) {
    const float* x       = (const float*)d_in[0];
    const float* w_ih    = (const float*)d_in[1];
    const float* w_hh    = (const float*)d_in[2];
    const float* b_ih    = (const float*)d_in[3];
    const float* b_hh    = (const float*)d_in[4];
    const float* dense_w = (const float*)d_in[5];
    const float* dense_b = (const float*)d_in[6];

    cudaFuncSetAttribute(lstm_persistent_kernel,
                         cudaFuncAttributeMaxDynamicSharedMemorySize, SMEM_W);
    quant_kernel<<<ROWS, 256>>>(w_hh);
    lstm_persistent_kernel<<<NBLK, NTHR, SMEM_W>>>(x, w_ih, b_ih, b_hh,
                                                   dense_w, dense_b, (float*)d_out);
}

// round 14
// speedup vs baseline: 1.0272x; 1.0272x over previous
#include <cuda_runtime.h>
#include <math.h>

#define SEQ   40
#define H     4096
#define OUT   128
#define NBLK  128
#define NTHR  1024
#define JPB   32                  // hidden indices per block (= warps per block)
#define RPB   128                 // rows per block (32 j x 4 gates)
#define ROWS  (4 * H)
#define CH_B  32768               // bytes per chunk (128 rows x 256 cols)
#define NCHUNK 16
#define SCH   6                   // chunks 0..5 resident in smem (192 KB)
#define BLOCK_WQ (RPB * H)        // 512 KB s8 weights per block
#define SMEM_W (SCH * CH_B)

// ---- persistent device state ----
__device__ float    g_h[H];                                      // fp32 h_last for dense
__device__ unsigned g_hq[2][H / 2];                              // ping-pong s16 h (u16[H])
__device__ float    g_scale[ROWS];                               // per-row dequant scale
__device__ __align__(256) unsigned char g_wq[(size_t)NBLK * BLOCK_WQ]; // 67MB s8
__device__ __align__(16) unsigned g_stamp[NBLK];                 // per-block step stamps

// ---------------- quant ----------------
// resident chunks (0..5):  [B][chunk][warp=j&31][pair=gate>>1: 512B][lane*16B]
// streamed chunks (6..15): [B][chunk][warp=j&31][lane*32B: {pair0 16B, pair1 16B}]
__global__ __launch_bounds__(256) void quant_kernel(const float* __restrict__ w_hh) {
    __shared__ float wmax[8];
    const int r    = blockIdx.x;             // gate row (gate*H + j)
    const int tid  = threadIdx.x;
    const int lane = tid & 31, wrp = tid >> 5;

    const float4* rp = (const float4*)(w_hh + (size_t)r * H) + tid * 4;
    const float4 vs[4] = {__ldg(rp), __ldg(rp + 1), __ldg(rp + 2), __ldg(rp + 3)};

    float m = 0.0f;
    #pragma unroll
    for (int q = 0; q < 4; ++q)
        m = fmaxf(m, fmaxf(fmaxf(fabsf(vs[q].x), fabsf(vs[q].y)),
                           fmaxf(fabsf(vs[q].z), fabsf(vs[q].w))));
    #pragma unroll
    for (int o = 16; o > 0; o >>= 1) m = fmaxf(m, __shfl_xor_sync(0xffffffffu, m, o));
    if (lane == 0) wmax[wrp] = m;
    __syncthreads();
    float mx = wmax[0];
    #pragma unroll
    for (int w = 1; w < 8; ++w) mx = fmaxf(mx, wmax[w]);
    if (tid == 0) g_scale[r] = mx * (1.0f / 127.0f);
    const float inv = (mx > 0.0f) ? 127.0f / mx : 0.0f;

    unsigned b[16];
    #pragma unroll
    for (int q = 0; q < 4; ++q) {
        b[4 * q + 0] = __float_as_uint(fmaf(vs[q].x, inv, 8388736.0f));
        b[4 * q + 1] = __float_as_uint(fmaf(vs[q].y, inv, 8388736.0f));
        b[4 * q + 2] = __float_as_uint(fmaf(vs[q].z, inv, 8388736.0f));
        b[4 * q + 3] = __float_as_uint(fmaf(vs[q].w, inv, 8388736.0f));
    }
    uint4 o;
    #pragma unroll
    for (int q = 0; q < 4; ++q) {
        unsigned t0 = __byte_perm(b[4 * q + 0], b[4 * q + 1], 0x0040);
        unsigned t1 = __byte_perm(b[4 * q + 2], b[4 * q + 3], 0x0040);
        ((unsigned*)&o)[q] = __byte_perm(t0, t1, 0x5410) ^ 0x80808080u;
    }
    const int j = r & (H - 1), gate = r >> 12;
    const int B = j >> 5;
    const int wid_ = j & 31;
    const int p = gate >> 1, rp_ = gate & 1;
    const int chunk = tid >> 4;
    const int T = tid & 15;                  // thread covers cols 16T..16T+15 -> lanes 2T,2T+1
    unsigned char* wbase = g_wq + (size_t)B * BLOCK_WQ + (size_t)chunk * CH_B + wid_ * 1024;
    if (chunk < SCH) {
        // resident layout
        unsigned char* dst = wbase + p * 512 + rp_ * 8;
        *(uint2*)(dst + (2 * T)     * 16) = make_uint2(o.x, o.y);
        *(uint2*)(dst + (2 * T + 1) * 16) = make_uint2(o.z, o.w);
    } else {
        // streamed layout: lane-contiguous 32B
        *(uint2*)(wbase + (2 * T)     * 32 + p * 16 + rp_ * 8) = make_uint2(o.x, o.y);
        *(uint2*)(wbase + (2 * T + 1) * 32 + p * 16 + rp_ * 8) = make_uint2(o.z, o.w);
    }
}

#define DOPAIR(p, Q) do {                                                 \
    acc[2*(p)]   = __dp2a_lo((int)hv.x, (int)(Q).x, acc[2*(p)]);          \
    acc[2*(p)]   = __dp2a_hi((int)hv.y, (int)(Q).x, acc[2*(p)]);          \
    acc[2*(p)]   = __dp2a_lo((int)hv.z, (int)(Q).y, acc[2*(p)]);          \
    acc[2*(p)]   = __dp2a_hi((int)hv.w, (int)(Q).y, acc[2*(p)]);          \
    acc[2*(p)+1] = __dp2a_lo((int)hv.x, (int)(Q).z, acc[2*(p)+1]);        \
    acc[2*(p)+1] = __dp2a_hi((int)hv.y, (int)(Q).z, acc[2*(p)+1]);        \
    acc[2*(p)+1] = __dp2a_lo((int)hv.z, (int)(Q).w, acc[2*(p)+1]);        \
    acc[2*(p)+1] = __dp2a_hi((int)hv.w, (int)(Q).w, acc[2*(p)+1]);        \
} while (0)

#define DOCHUNK_SM(cc) do {                                               \
    const uint4 hv = *(const uint4*)(hq + (cc) * 128 + 4 * lane);         \
    const unsigned char* _c = wsm + (size_t)(cc) * CH_B + wid * 1024 + lane * 16; \
    const uint4 q0 = *(const uint4*)(_c);                                 \
    const uint4 q1 = *(const uint4*)(_c + 512);                           \
    DOPAIR(0, q0); DOPAIR(1, q1);                                         \
} while (0)

#define DOCHUNK_SB(cc, SB) do {                                           \
    const uint4 hv = *(const uint4*)(hq + (cc) * 128 + 4 * lane);         \
    DOPAIR(0, SB[0]); DOPAIR(1, SB[1]);                                   \
} while (0)

// one 256-bit load per streamed chunk per warp
#define LDSB(dst, cc) do {                                                \
    const unsigned char* _p = wsrc + (size_t)(cc) * CH_B + wid * 1024 + lane * 32; \
    asm volatile("ld.global.nc.v8.b32 {%0,%1,%2,%3,%4,%5,%6,%7}, [%8];"   \
        : "=r"(dst[0].x), "=r"(dst[0].y), "=r"(dst[0].z), "=r"(dst[0].w), \
          "=r"(dst[1].x), "=r"(dst[1].y), "=r"(dst[1].z), "=r"(dst[1].w)  \
        : "l"(_p)); } while (0)

__device__ __forceinline__ float sigf(float v) { return 1.0f / (1.0f + __expf(-v)); }

// ---------------- persistent LSTM kernel ----------------
__global__ __launch_bounds__(NTHR, 1)
void lstm_persistent_kernel(const float* __restrict__ x,
                            const float* __restrict__ w_ih,
                            const float* __restrict__ b_ih,
                            const float* __restrict__ b_hh,
                            const float* __restrict__ dense_w,
                            const float* __restrict__ dense_b,
                            float* __restrict__ out) {
    extern __shared__ unsigned char wsm[];       // 192 KB resident weights (chunks 0..5)
    __shared__ unsigned hq[H / 2];               // 8 KB packed h_{t-1}
    __shared__ float xs[SEQ];
    __shared__ float red[NTHR / 32];

    const int tid  = threadIdx.x;
    const int lane = tid & 31;
    const int wid  = tid >> 5;                   // warp owns j = j0 + wid (all 4 gates)
    const int j0   = blockIdx.x * JPB;
    const int j    = j0 + wid;
    const unsigned char* wsrc = g_wq + (size_t)blockIdx.x * BLOCK_WQ;

    // per-lane gate constants: lane g (mod 4) holds gate g's scalars
    const int grow = (lane & 3) * H + j;
    const float wih_l  = __ldg(w_ih + grow);
    const float bsum_l = __ldg(b_ih + grow) + __ldg(b_hh + grow);
    const float scl_l  = __ldg(g_scale + grow) * (1.0f / 32767.0f);
    if (tid < SEQ) xs[tid] = x[tid];

    // copy smem-resident chunks 0..5
    {
        const uint4* gsrc = (const uint4*)wsrc;
        uint4* d = (uint4*)wsm;
        #pragma unroll
        for (int i = 0; i < SMEM_W / 16 / NTHR; ++i)
            d[tid + i * NTHR] = __ldg(gsrc + tid + i * NTHR);
    }

    const unsigned base = *(volatile unsigned*)&g_stamp[blockIdx.x];
    float c_reg = 0.0f;

    for (int t = 0; t < SEQ; ++t) {
        int rsel = 0;
        if (t > 0) {
            // prefetch first four streamed chunks (independent of h)
            uint4 sb0[2], sb1[2], sb2[2], sb3[2];
            LDSB(sb0, 6); LDSB(sb1, 7); LDSB(sb2, 8); LDSB(sb3, 9);

            // fine-grained staging: thread tid waits only for ITS piece's producer
            if (tid < 512) {
                const unsigned* sp = &g_stamp[tid >> 2];
                unsigned s;
                do {
                    asm volatile("ld.acquire.gpu.global.u32 %0, [%1];"
                                 : "=r"(s) : "l"(sp));
                } while (s - base < (unsigned)t);
                ((uint4*)hq)[tid] = ((const uint4*)g_hq[(t - 1) & 1])[tid];
            }
            __syncthreads();                     // bar A: hq fully staged

            int acc[4] = {0, 0, 0, 0};
            DOCHUNK_SM(0); DOCHUNK_SM(1); DOCHUNK_SM(2);
            DOCHUNK_SM(3); DOCHUNK_SM(4); DOCHUNK_SM(5);
            DOCHUNK_SB(6,  sb0); LDSB(sb0, 10);
            DOCHUNK_SB(7,  sb1); LDSB(sb1, 11);
            DOCHUNK_SB(8,  sb2); LDSB(sb2, 12);
            DOCHUNK_SB(9,  sb3); LDSB(sb3, 13);
            DOCHUNK_SB(10, sb0); LDSB(sb0, 14);
            DOCHUNK_SB(11, sb1); LDSB(sb1, 15);
            DOCHUNK_SB(12, sb2);
            DOCHUNK_SB(13, sb3);
            DOCHUNK_SB(14, sb0);
            DOCHUNK_SB(15, sb1);

            const int r0 = __reduce_add_sync(0xffffffffu, acc[0]);
            const int r1 = __reduce_add_sync(0xffffffffu, acc[1]);
            const int r2 = __reduce_add_sync(0xffffffffu, acc[2]);
            const int r3 = __reduce_add_sync(0xffffffffu, acc[3]);
            rsel = (lane == 1) ? r1 : (lane == 2) ? r2 : (lane == 3) ? r3 : r0;
        }

        // gate-parallel tail: lanes 0..3 evaluate their gate's activation
        {
            const float xt = xs[t];
            const float v  = fmaf(wih_l, xt, bsum_l) + __int2float_rn(rsel) * scl_l;
            const float act = (lane == 2) ? tanhf(v) : sigf(v);
            const float a1 = __shfl_sync(0xffffffffu, act, 1);
            const float a2 = __shfl_sync(0xffffffffu, act, 2);
            const float a3 = __shfl_sync(0xffffffffu, act, 3);
            if (lane == 0) {
                const float c = a1 * c_reg + act * a2;   // sig(f)*c + sig(i)*tanh(g)
                c_reg = c;
                const float h = a3 * tanhf(c);
                ((unsigned short*)g_hq[t & 1])[j] =
                    (unsigned short)(short)__float2int_rn(h * 32767.0f);
                if (t == SEQ - 1) g_h[j] = h;
            }
        }
        __syncthreads();                         // bar B: all h stored (CTA-visible)
        if (tid == 0) {
            asm volatile("membar.gl;" ::: "memory");   // single gpu-scope fence
            *(volatile unsigned*)&g_stamp[blockIdx.x] = base + (unsigned)(t + 1);
        }
    }

    // final sync: all blocks published h_last
    if (wid == 0) {
        const unsigned* sp = g_stamp + lane * 4;
        for (;;) {
            unsigned s0, s1, s2, s3;
            asm volatile("ld.volatile.global.v4.u32 {%0,%1,%2,%3}, [%4];"
                         : "=r"(s0), "=r"(s1), "=r"(s2), "=r"(s3) : "l"(sp));
            const bool ok = (s0 - base) >= SEQ && (s1 - base) >= SEQ
                         && (s2 - base) >= SEQ && (s3 - base) >= SEQ;
            if (__all_sync(0xffffffffu, ok)) break;
        }
        __threadfence();
    }
    __syncthreads();

    // dense epilogue: block b computes out[b] (NBLK == OUT)
    {
        const float* hw = g_h;
        const float* wr = dense_w + (size_t)blockIdx.x * H;
        float acc = 0.0f;
        #pragma unroll
        for (int k = tid; k < H; k += NTHR)
            acc += wr[k] * hw[k];
        #pragma unroll
        for (int o = 16; o > 0; o >>= 1)
            acc += __shfl_down_sync(0xffffffffu, acc, o);
        if (lane == 0) red[wid] = acc;
        __syncthreads();
        if (tid == 0) {
            float s = 0.0f;
            #pragma unroll
            for (int w = 0; w < NTHR / 32; ++w) s += red[w];
            out[blockIdx.x] = s + dense_b[blockIdx.x];
        }
    }
}

extern "C" void kernel_launch(void* const* d_in, const int* in_sizes, int n_in,
                              void* d_out, int out_size) {
    const float* x       = (const float*)d_in[0];
    const float* w_ih    = (const float*)d_in[1];
    const float* w_hh    = (const float*)d_in[2];
    const float* b_ih    = (const float*)d_in[3];
    const float* b_hh    = (const float*)d_in[4];
    const float* dense_w = (const float*)d_in[5];
    const float* dense_b = (const float*)d_in[6];

    cudaFuncSetAttribute(lstm_persistent_kernel,
                         cudaFuncAttributeMaxDynamicSharedMemorySize, SMEM_W);
    quant_kernel<<<ROWS, 256>>>(w_hh);
    lstm_persistent_kernel<<<NBLK, NTHR, SMEM_W>>>(x, w_ih, b_ih, b_hh,
                                                   dense_w, dense_b, (float*)d_out);
}

// round 15
// speedup vs baseline: 2.0829x; 2.0277x over previous
#include <cuda_runtime.h>
#include <math.h>

#define SEQ   40
#define H     4096
#define OUT   128
#define NBLK  128
#define NTHR  1024
#define JPB   32                  // hidden indices per block (= warps per block)
#define RPB   128                 // rows per block (32 j x 4 gates)
#define ROWS  (4 * H)
#define CH_B  32768               // bytes per chunk (128 rows x 256 cols)
#define NCHUNK 16
#define SCH   6                   // chunks 0..5 resident in smem (192 KB)
#define BLOCK_WQ (RPB * H)        // 512 KB s8 weights per block
#define SMEM_W (SCH * CH_B)

// ---- persistent device state ----
__device__ float    g_h[H];                                      // fp32 h_last for dense
__device__ unsigned g_hq[2][H / 2];                              // ping-pong s16 h (u16[H])
__device__ float    g_scale[ROWS];                               // per-row dequant scale
__device__ __align__(256) unsigned char g_wq[(size_t)NBLK * BLOCK_WQ]; // 67MB s8
__device__ __align__(16) unsigned g_stamp[NBLK];                 // per-block step stamps

// ---------------- quant; paired-row layout (identical to the 299.7us kernel) ----------------
// [B=j>>5][chunk][warp=j&31][pair=gate>>1][lane 16B: rows(2p,2p+1) cols 8l..8l+7]
__global__ __launch_bounds__(256) void quant_kernel(const float* __restrict__ w_hh) {
    __shared__ float wmax[8];
    const int r    = blockIdx.x;             // gate row (gate*H + j)
    const int tid  = threadIdx.x;
    const int lane = tid & 31, wrp = tid >> 5;

    const float4* rp = (const float4*)(w_hh + (size_t)r * H) + tid * 4;
    const float4 vs[4] = {__ldg(rp), __ldg(rp + 1), __ldg(rp + 2), __ldg(rp + 3)};

    float m = 0.0f;
    #pragma unroll
    for (int q = 0; q < 4; ++q)
        m = fmaxf(m, fmaxf(fmaxf(fabsf(vs[q].x), fabsf(vs[q].y)),
                           fmaxf(fabsf(vs[q].z), fabsf(vs[q].w))));
    #pragma unroll
    for (int o = 16; o > 0; o >>= 1) m = fmaxf(m, __shfl_xor_sync(0xffffffffu, m, o));
    if (lane == 0) wmax[wrp] = m;
    __syncthreads();
    float mx = wmax[0];
    #pragma unroll
    for (int w = 1; w < 8; ++w) mx = fmaxf(mx, wmax[w]);
    if (tid == 0) g_scale[r] = mx * (1.0f / 127.0f);
    const float inv = (mx > 0.0f) ? 127.0f / mx : 0.0f;

    unsigned b[16];
    #pragma unroll
    for (int q = 0; q < 4; ++q) {
        b[4 * q + 0] = __float_as_uint(fmaf(vs[q].x, inv, 8388736.0f));
        b[4 * q + 1] = __float_as_uint(fmaf(vs[q].y, inv, 8388736.0f));
        b[4 * q + 2] = __float_as_uint(fmaf(vs[q].z, inv, 8388736.0f));
        b[4 * q + 3] = __float_as_uint(fmaf(vs[q].w, inv, 8388736.0f));
    }
    uint4 o;
    #pragma unroll
    for (int q = 0; q < 4; ++q) {
        unsigned t0 = __byte_perm(b[4 * q + 0], b[4 * q + 1], 0x0040);
        unsigned t1 = __byte_perm(b[4 * q + 2], b[4 * q + 3], 0x0040);
        ((unsigned*)&o)[q] = __byte_perm(t0, t1, 0x5410) ^ 0x80808080u;
    }
    const int j = r & (H - 1), gate = r >> 12;
    const int B = j >> 5;
    const int wid_ = j & 31;
    const int p = gate >> 1, rp_ = gate & 1;
    const int chunk = tid >> 4;
    const int lpos = (tid & 15) * 2;         // first of two dest lanes
    unsigned char* dst = g_wq + (size_t)B * BLOCK_WQ + (size_t)chunk * CH_B
                       + wid_ * 1024 + p * 512 + rp_ * 8;
    *(uint2*)(dst + lpos * 16)       = make_uint2(o.x, o.y);   // cols 16T..16T+7
    *(uint2*)(dst + (lpos + 1) * 16) = make_uint2(o.z, o.w);   // cols 16T+8..+15
}

// pair uint4 Q holds rows (2p, 2p+1): Q.x/Q.y = row 2p, Q.z/Q.w = row 2p+1
#define DOPAIR(p, Q, HV) do {                                             \
    acc[2*(p)]   = __dp2a_lo((int)(HV).x, (int)(Q).x, acc[2*(p)]);        \
    acc[2*(p)]   = __dp2a_hi((int)(HV).y, (int)(Q).x, acc[2*(p)]);        \
    acc[2*(p)]   = __dp2a_lo((int)(HV).z, (int)(Q).y, acc[2*(p)]);        \
    acc[2*(p)]   = __dp2a_hi((int)(HV).w, (int)(Q).y, acc[2*(p)]);        \
    acc[2*(p)+1] = __dp2a_lo((int)(HV).x, (int)(Q).z, acc[2*(p)+1]);      \
    acc[2*(p)+1] = __dp2a_hi((int)(HV).y, (int)(Q).z, acc[2*(p)+1]);      \
    acc[2*(p)+1] = __dp2a_lo((int)(HV).z, (int)(Q).w, acc[2*(p)+1]);      \
    acc[2*(p)+1] = __dp2a_hi((int)(HV).w, (int)(Q).w, acc[2*(p)+1]);      \
} while (0)

#define LDH(cc) (*(const uint4*)(hq + (cc) * 128 + 4 * lane))

#define DOCHUNK_SM(cc, HV) do {                                           \
    const unsigned char* _c = wsm + (size_t)(cc) * CH_B + wid * 1024 + lane * 16; \
    const uint4 q0 = *(const uint4*)(_c);                                 \
    const uint4 q1 = *(const uint4*)(_c + 512);                           \
    DOPAIR(0, q0, HV); DOPAIR(1, q1, HV);                                 \
} while (0)

#define DOCHUNK_SB(SB, HV) do {                                           \
    DOPAIR(0, SB[0], HV); DOPAIR(1, SB[1], HV);                           \
} while (0)

#define LDSB(dst, cc) do {                                                \
    const unsigned char* _p = wsrc + (size_t)(cc) * CH_B + wid * 1024 + lane * 16; \
    dst[0] = __ldg((const uint4*)(_p));                                   \
    dst[1] = __ldg((const uint4*)(_p + 512)); } while (0)

__device__ __forceinline__ float sigf(float v) { return 1.0f / (1.0f + __expf(-v)); }

// ---------------- persistent LSTM kernel ----------------
__global__ __launch_bounds__(NTHR, 1)
void lstm_persistent_kernel(const float* __restrict__ x,
                            const float* __restrict__ w_ih,
                            const float* __restrict__ b_ih,
                            const float* __restrict__ b_hh,
                            const float* __restrict__ dense_w,
                            const float* __restrict__ dense_b,
                            float* __restrict__ out) {
    extern __shared__ unsigned char wsm[];       // 192 KB resident weights (chunks 0..5)
    __shared__ unsigned hq[H / 2];               // 8 KB packed h_{t-1}
    __shared__ float xs[SEQ];
    __shared__ float red[NTHR / 32];

    const int tid  = threadIdx.x;
    const int lane = tid & 31;
    const int wid  = tid >> 5;                   // warp owns j = j0 + wid (all 4 gates)
    const int j0   = blockIdx.x * JPB;
    const int j    = j0 + wid;
    const unsigned char* wsrc = g_wq + (size_t)blockIdx.x * BLOCK_WQ;

    // per-lane gate constants: lane g (mod 4) holds gate g's scalars
    const int grow = (lane & 3) * H + j;
    const float wih_l  = __ldg(w_ih + grow);
    const float bsum_l = __ldg(b_ih + grow) + __ldg(b_hh + grow);
    const float scl_l  = __ldg(g_scale + grow) * (1.0f / 32767.0f);
    if (tid < SEQ) xs[tid] = x[tid];

    // copy smem-resident chunks 0..5
    {
        const uint4* gsrc = (const uint4*)wsrc;
        uint4* d = (uint4*)wsm;
        #pragma unroll
        for (int i = 0; i < SMEM_W / 16 / NTHR; ++i)
            d[tid + i * NTHR] = __ldg(gsrc + tid + i * NTHR);
    }

    const unsigned base = *(volatile unsigned*)&g_stamp[blockIdx.x];
    float c_reg = 0.0f;

    for (int t = 0; t < SEQ; ++t) {
        int rsel = 0;
        if (t > 0) {
            // prefetch first four streamed chunks (independent of h)
            uint4 sb0[2], sb1[2], sb2[2], sb3[2];
            LDSB(sb0, 6); LDSB(sb1, 7); LDSB(sb2, 8); LDSB(sb3, 9);

            // fine-grained staging: thread tid waits only for ITS piece's producer
            if (tid < 512) {
                const unsigned* sp = &g_stamp[tid >> 2];
                unsigned s;
                do {
                    asm volatile("ld.acquire.gpu.global.u32 %0, [%1];"
                                 : "=r"(s) : "l"(sp));
                } while (s - base < (unsigned)t);
                ((uint4*)hq)[tid] = ((const uint4*)g_hq[(t - 1) & 1])[tid];
            }
            __syncthreads();                     // bar A: hq fully staged

            int acc[4] = {0, 0, 0, 0};
            // software-pipelined h loads: hvn always one chunk ahead
            uint4 hv = LDH(0), hvn;
            hvn = LDH(1);  DOCHUNK_SM(0, hv);  hv = hvn;
            hvn = LDH(2);  DOCHUNK_SM(1, hv);  hv = hvn;
            hvn = LDH(3);  DOCHUNK_SM(2, hv);  hv = hvn;
            hvn = LDH(4);  DOCHUNK_SM(3, hv);  hv = hvn;
            hvn = LDH(5);  DOCHUNK_SM(4, hv);  hv = hvn;
            hvn = LDH(6);  DOCHUNK_SM(5, hv);  hv = hvn;
            hvn = LDH(7);  DOCHUNK_SB(sb0, hv); LDSB(sb0, 10); hv = hvn;
            hvn = LDH(8);  DOCHUNK_SB(sb1, hv); LDSB(sb1, 11); hv = hvn;
            hvn = LDH(9);  DOCHUNK_SB(sb2, hv); LDSB(sb2, 12); hv = hvn;
            hvn = LDH(10); DOCHUNK_SB(sb3, hv); LDSB(sb3, 13); hv = hvn;
            hvn = LDH(11); DOCHUNK_SB(sb0, hv); LDSB(sb0, 14); hv = hvn;
            hvn = LDH(12); DOCHUNK_SB(sb1, hv); LDSB(sb1, 15); hv = hvn;
            hvn = LDH(13); DOCHUNK_SB(sb2, hv); hv = hvn;
            hvn = LDH(14); DOCHUNK_SB(sb3, hv); hv = hvn;
            hvn = LDH(15); DOCHUNK_SB(sb0, hv); hv = hvn;
            DOCHUNK_SB(sb1, hv);

            const int r0 = __reduce_add_sync(0xffffffffu, acc[0]);
            const int r1 = __reduce_add_sync(0xffffffffu, acc[1]);
            const int r2 = __reduce_add_sync(0xffffffffu, acc[2]);
            const int r3 = __reduce_add_sync(0xffffffffu, acc[3]);
            rsel = (lane == 1) ? r1 : (lane == 2) ? r2 : (lane == 3) ? r3 : r0;
        }

        // gate-parallel tail: lanes 0..3 evaluate their gate's activation
        {
            const float xt = xs[t];
            const float v  = fmaf(wih_l, xt, bsum_l) + __int2float_rn(rsel) * scl_l;
            const float act = (lane == 2) ? tanhf(v) : sigf(v);
            const float a1 = __shfl_sync(0xffffffffu, act, 1);
            const float a2 = __shfl_sync(0xffffffffu, act, 2);
            const float a3 = __shfl_sync(0xffffffffu, act, 3);
            if (lane == 0) {
                const float c = a1 * c_reg + act * a2;   // sig(f)*c + sig(i)*tanh(g)
                c_reg = c;
                const float h = a3 * tanhf(c);
                ((unsigned short*)g_hq[t & 1])[j] =
                    (unsigned short)(short)__float2int_rn(h * 32767.0f);
                if (t == SEQ - 1) g_h[j] = h;
                asm volatile("membar.gl;" ::: "memory");
            }
        }
        __syncthreads();                         // bar B: all h stored+fenced
        if (tid == 0)
            *(volatile unsigned*)&g_stamp[blockIdx.x] = base + (unsigned)(t + 1);
    }

    // final sync: all blocks published h_last
    if (wid == 0) {
        const unsigned* sp = g_stamp + lane * 4;
        for (;;) {
            unsigned s0, s1, s2, s3;
            asm volatile("ld.volatile.global.v4.u32 {%0,%1,%2,%3}, [%4];"
                         : "=r"(s0), "=r"(s1), "=r"(s2), "=r"(s3) : "l"(sp));
            const bool ok = (s0 - base) >= SEQ && (s1 - base) >= SEQ
                         && (s2 - base) >= SEQ && (s3 - base) >= SEQ;
            if (__all_sync(0xffffffffu, ok)) break;
        }
        __threadfence();
    }
    __syncthreads();

    // dense epilogue: block b computes out[b] (NBLK == OUT)
    {
        const float* hw = g_h;
        const float* wr = dense_w + (size_t)blockIdx.x * H;
        float acc = 0.0f;
        #pragma unroll
        for (int k = tid; k < H; k += NTHR)
            acc += wr[k] * hw[k];
        #pragma unroll
        for (int o = 16; o > 0; o >>= 1)
            acc += __shfl_down_sync(0xffffffffu, acc, o);
        if (lane == 0) red[wid] = acc;
        __syncthreads();
        if (tid == 0) {
            float s = 0.0f;
            #pragma unroll
            for (int w = 0; w < NTHR / 32; ++w) s += red[w];
            out[blockIdx.x] = s + dense_b[blockIdx.x];
        }
    }
}

extern "C" void kernel_launch(void* const* d_in, const int* in_sizes, int n_in,
                              void* d_out, int out_size) {
    const float* x       = (const float*)d_in[0];
    const float* w_ih    = (const float*)d_in[1];
    const float* w_hh    = (const float*)d_in[2];
    const float* b_ih    = (const float*)d_in[3];
    const float* b_hh    = (const float*)d_in[4];
    const float* dense_w = (const float*)d_in[5];
    const float* dense_b = (const float*)d_in[6];

    cudaFuncSetAttribute(lstm_persistent_kernel,
                         cudaFuncAttributeMaxDynamicSharedMemorySize, SMEM_W);
    quant_kernel<<<ROWS, 256>>>(w_hh);
    lstm_persistent_kernel<<<NBLK, NTHR, SMEM_W>>>(x, w_ih, b_ih, b_hh,
                                                   dense_w, dense_b, (float*)d_out);
}